// round 8
// baseline (speedup 1.0000x reference)
#include <cuda_runtime.h>
#include <math.h>
#include <float.h>

// Problem dims
#define NB 128
#define ND 256
#define NS 512
#define NK 50
#define NH 256
#define NROWS (NB*NS)            // 65536 (b,s) rows
#define OUT_PRED 0
#define OUT_SCAL0 256
#define OUT_SIM 257
#define OUT_FAR 258
#define OUT_NN 259               // B*S*K floats
#define OUT_AE (259 + NROWS*NK)

typedef unsigned long long ull;

// ---------------- packed f32x2 helpers (FFMA2) ----------------
__device__ __forceinline__ ull pack_dup(float a) {
    ull r; asm("mov.b64 %0, {%1, %1};" : "=l"(r) : "f"(a)); return r;
}
__device__ __forceinline__ void ffma2(ull &c, ull a, ull b) {
    asm("fma.rn.f32x2 %0, %1, %2, %0;" : "+l"(c) : "l"(a), "l"(b));
}
__device__ __forceinline__ float2 unpack2(ull v) {
    float2 f; asm("mov.b64 {%0, %1}, %2;" : "=f"(f.x), "=f"(f.y) : "l"(v)); return f;
}

// ---------------- device scratch ----------------
__device__ __align__(16) float g_tvn[ND*NK];
__device__ __align__(16) float g_tvnp[ND*64];     // padded [D][64]
__device__ __align__(16) float g_invnorm[NROWS];
__device__ __align__(16) float g_tpnT[NK*NROWS];  // [K][B*S]
__device__ __align__(16) float g_nnT[NK*NROWS];   // nn transposed [K][B*S]
__device__ __align__(16) float g_rec1[NROWS*NH];
__device__ __align__(16) float g_mean[NB*ND];
__device__ float g_ae;
__device__ float g_sim;
__device__ float g_far;

// ---------------- kernel 0: prep ----------------
__global__ void prep_kernel(const float* __restrict__ tv) {
    __shared__ float inv[64];
    __shared__ float red[256];
    int tid = threadIdx.x;
    if (tid < NK) {
        float ss = 0.f;
        for (int d = 0; d < ND; d++) { float v = tv[d*NK + tid]; ss += v*v; }
        inv[tid] = 1.0f / fmaxf(sqrtf(ss), 1e-12f);
    }
    __syncthreads();
    for (int i = tid; i < ND*NK; i += 256) g_tvn[i] = tv[i] * inv[i % NK];
    for (int i = tid; i < NB*ND; i += 256) g_mean[i] = 0.f;
    if (tid == 0) { g_ae = 0.f; g_sim = 0.f; }
    __syncthreads();
    for (int i = tid; i < ND*64; i += 256) {
        int d = i >> 6, k = i & 63;
        g_tvnp[i] = (k < NK) ? g_tvn[d*NK + k] : 0.f;
    }
    float acc = 0.f;
    for (int p = tid; p < NK*NK; p += 256) {
        int i = p / NK, j = p % NK;
        float ds = 0.f;
        for (int d = 0; d < ND; d++) ds += g_tvn[d*NK + i] * g_tvn[d*NK + j];
        acc += ds - ((i == j) ? 1.0f : 0.0f);
    }
    red[tid] = acc; __syncthreads();
    for (int s = 128; s > 0; s >>= 1) { if (tid < s) red[tid] += red[tid+s]; __syncthreads(); }
    if (tid == 0) g_far = red[0] / (float)(NK*NK);
}

// ---------------- kernel 1: topic GEMM 128x64xK256 + fused norm/mask/nn ----------------
// 256 thr: tx = tid&15 (16 col groups of 4), ty = tid>>4 (16 row groups of 8). micro 8x4.
__global__ void __launch_bounds__(256, 3) topic_kernel(const float* __restrict__ f,
                                                       float* __restrict__ out_nn) {
    __shared__ float As[16*128];          // [kk][row]
    __shared__ ull   Bsd[16*64];          // [kk][col] pre-duplicated f32x2
    __shared__ float spart[128*16];
    __shared__ float inv_s[128];
    __shared__ float den_s[128];

    int tid = threadIdx.x;
    int tx = tid & 15, ty = tid >> 4;
    int row0 = blockIdx.x * 128;
    int b = row0 >> 9;
    int s00 = row0 & 511;

    ull acc2[4][4];
    #pragma unroll
    for (int p = 0; p < 4; p++)
        #pragma unroll
        for (int j = 0; j < 4; j++) acc2[p][j] = 0ull;
    float ssq[8];
    #pragma unroll
    for (int i = 0; i < 8; i++) ssq[i] = 0.f;

    for (int d0 = 0; d0 < ND; d0 += 16) {
        #pragma unroll
        for (int it = 0; it < 2; it++) {
            int v = tid + it*256;
            int kk = v >> 5, r4 = (v & 31) * 4;
            float4 t4 = *(const float4*)(f + ((size_t)(b*ND + d0 + kk))*NS + s00 + r4);
            *(float4*)&As[kk*128 + r4] = t4;
        }
        {
            int kk = tid >> 4, c4 = (tid & 15) * 4;
            float4 t4 = *(const float4*)&g_tvnp[(d0 + kk)*64 + c4];
            ulonglong2 d0v, d1v;
            d0v.x = pack_dup(t4.x); d0v.y = pack_dup(t4.y);
            d1v.x = pack_dup(t4.z); d1v.y = pack_dup(t4.w);
            *(ulonglong2*)&Bsd[kk*64 + c4]     = d0v;
            *(ulonglong2*)&Bsd[kk*64 + c4 + 2] = d1v;
        }
        __syncthreads();
        #pragma unroll
        for (int kk = 0; kk < 16; kk++) {
            ulonglong2 aA = *(const ulonglong2*)&As[kk*128 + ty*8];
            ulonglong2 aB = *(const ulonglong2*)&As[kk*128 + ty*8 + 4];
            ull av[4] = {aA.x, aA.y, aB.x, aB.y};
            ulonglong2 b0 = *(const ulonglong2*)&Bsd[kk*64 + tx*4];
            ulonglong2 b1 = *(const ulonglong2*)&Bsd[kk*64 + tx*4 + 2];
            ull bv[4] = {b0.x, b0.y, b1.x, b1.y};
            #pragma unroll
            for (int p = 0; p < 4; p++) {
                #pragma unroll
                for (int j = 0; j < 4; j++) ffma2(acc2[p][j], av[p], bv[j]);
            }
            if (tx == 0) {
                #pragma unroll
                for (int p = 0; p < 4; p++) {
                    float2 c = unpack2(av[p]);
                    ssq[2*p]   += c.x*c.x;
                    ssq[2*p+1] += c.y*c.y;
                }
            }
        }
        __syncthreads();
    }

    if (tx == 0) {
        #pragma unroll
        for (int i = 0; i < 8; i++) {
            float iv = 1.0f / fmaxf(sqrtf(ssq[i]), 1e-12f);
            inv_s[ty*8 + i] = iv;
            g_invnorm[row0 + ty*8 + i] = iv;
        }
    }
    __syncthreads();

    // unpack: acc2[p][j] = rows (ty*8+2p, +2p+1), col tx*4+j
    float tp[8][4], amv[8][4], iv[8];
    #pragma unroll
    for (int i = 0; i < 8; i++) iv[i] = inv_s[ty*8 + i];
    #pragma unroll
    for (int p = 0; p < 4; p++)
        #pragma unroll
        for (int j = 0; j < 4; j++) {
            float2 c = unpack2(acc2[p][j]);
            tp[2*p][j]   = c.x;
            tp[2*p+1][j] = c.y;
        }
    #pragma unroll
    for (int i = 0; i < 8; i++) {
        float psum = 0.f;
        #pragma unroll
        for (int j = 0; j < 4; j++) {
            float t = tp[i][j] * iv[i];
            float am = (t > 0.3f) ? tp[i][j] : 0.f;
            amv[i][j] = am;
            psum += am;                 // pad cols exactly 0
        }
        spart[(ty*8 + i)*16 + tx] = psum;
    }
    __syncthreads();
    if (tid < 128) {
        float s = 0.f;
        #pragma unroll
        for (int t = 0; t < 16; t++) s += spart[tid*16 + t];
        den_s[tid] = 1.0f / ((s + 0.001f) + 1e-8f);
    }
    __syncthreads();

    #pragma unroll
    for (int i = 0; i < 8; i++) {
        int row = row0 + ty*8 + i;
        float den = den_s[ty*8 + i];
        #pragma unroll
        for (int j = 0; j < 4; j++) {
            int k = tx*4 + j;
            if (k < NK) {
                float v = amv[i][j] * den;
                out_nn[(size_t)row*NK + k] = v;
                g_nnT[(size_t)k*NROWS + row] = v;
                g_tpnT[(size_t)k*NROWS + row] = tp[i][j] * iv[i];
            }
        }
    }
}

// ---------------- radix top-32 select per concept ----------------
#define TSEL_CAP 16384
#define TSEL_SMEM ((4096 + 1024 + TSEL_CAP + 1024 + 1024) * 4)
__global__ void __launch_bounds__(1024) topsel_kernel() {
    extern __shared__ unsigned smu[];
    unsigned* hist  = smu;
    unsigned* sscan = smu + 4096;
    float*    buf   = (float*)(smu + 5120);
    float*    red   = buf + TSEL_CAP;
    int*      ridx  = (int*)(red + 1024);
    __shared__ unsigned s_cnt, s_T, s_cntAbove, s_g;
    __shared__ float s_above;

    int tid = threadIdx.x;
    int k = blockIdx.x;
    const float* src = g_tpnT + (size_t)k * NROWS;

    for (int i = tid; i < 4096; i += 1024) hist[i] = 0u;
    if (tid == 0) s_cnt = 0u;
    __syncthreads();

    for (int i = tid; i < NROWS; i += 1024) {
        unsigned u = __float_as_uint(src[i]);
        u = (u & 0x80000000u) ? ~u : (u | 0x80000000u);
        atomicAdd(&hist[u >> 20], 1u);
    }
    __syncthreads();

    unsigned gsum = hist[4*tid] + hist[4*tid+1] + hist[4*tid+2] + hist[4*tid+3];
    sscan[tid] = gsum;
    __syncthreads();
    for (int off = 1; off < 1024; off <<= 1) {
        unsigned add = (tid + off < 1024) ? sscan[tid + off] : 0u;
        __syncthreads();
        sscan[tid] += add;
        __syncthreads();
    }
    {
        unsigned Sh = sscan[tid];
        unsigned Sn = (tid < 1023) ? sscan[tid + 1] : 0u;
        if (Sh >= 32u && Sn < 32u) s_g = (unsigned)tid;
    }
    __syncthreads();
    if (tid == 0) {
        int g = (int)s_g;
        unsigned cum = (g < 1023) ? sscan[g + 1] : 0u;
        for (int bb = 4*g + 3; bb >= 4*g; bb--) {
            unsigned h = hist[bb];
            if (cum + h >= 32u) { s_T = (unsigned)bb; s_cntAbove = cum; break; }
            cum += h;
        }
    }
    __syncthreads();
    unsigned T = s_T;

    float sumAbove = 0.f;
    for (int i = tid; i < NROWS; i += 1024) {
        float v = src[i];
        unsigned u = __float_as_uint(v);
        u = (u & 0x80000000u) ? ~u : (u | 0x80000000u);
        unsigned bn = u >> 20;
        if (bn > T) sumAbove += v;
        else if (bn == T) {
            unsigned p = atomicAdd(&s_cnt, 1u);
            if (p < TSEL_CAP) buf[p] = v;
        }
    }
    red[tid] = sumAbove;
    __syncthreads();
    for (int s = 512; s > 0; s >>= 1) { if (tid < s) red[tid] += red[tid+s]; __syncthreads(); }
    if (tid == 0) s_above = red[0];
    __syncthreads();

    int n = (int)min(s_cnt, (unsigned)TSEL_CAP);
    int need = 32 - (int)s_cntAbove;
    float picked = 0.f;
    for (int it = 0; it < need; it++) {
        float lm = -FLT_MAX; int li = 0;
        for (int j = tid; j < n; j += 1024) { float x = buf[j]; if (x > lm) { lm = x; li = j; } }
        red[tid] = lm; ridx[tid] = li;
        __syncthreads();
        for (int s = 512; s > 0; s >>= 1) {
            if (tid < s && red[tid+s] > red[tid]) { red[tid] = red[tid+s]; ridx[tid] = ridx[tid+s]; }
            __syncthreads();
        }
        if (tid == 0) { picked += red[0]; buf[ridx[0]] = -FLT_MAX; }
        __syncthreads();
    }
    if (tid == 0) atomicAdd(&g_sim, s_above + picked);
}

// ---------------- kernel 2: rec1 GEMM 128x64xK50, relu ----------------
// grid (4, 512). dyn smem: As[50*128]f | Bsd[50*64]ull. micro 8x4.
#define REC1_SMEM (NK*128*4 + NK*64*8)
__global__ void __launch_bounds__(256, 4) rec1_kernel(const float* __restrict__ rv1) {
    extern __shared__ float sm[];
    float* As  = sm;                    // [k][row]
    ull*   Bsd = (ull*)(sm + NK*128);   // [k][col] dup
    int tid = threadIdx.x;
    int tx = tid & 15, ty = tid >> 4;
    int col0 = blockIdx.x * 64;
    int row0 = blockIdx.y * 128;

    for (int v = tid; v < 1600; v += 256) {
        int k = v >> 5, r4 = (v & 31) * 4;
        *(float4*)&As[k*128 + r4] = *(const float4*)&g_nnT[(size_t)k*NROWS + row0 + r4];
    }
    for (int v = tid; v < 800; v += 256) {
        int k = v >> 4, c4 = (v & 15) * 4;
        float4 t4 = *(const float4*)(rv1 + k*NH + col0 + c4);
        ulonglong2 d0v, d1v;
        d0v.x = pack_dup(t4.x); d0v.y = pack_dup(t4.y);
        d1v.x = pack_dup(t4.z); d1v.y = pack_dup(t4.w);
        *(ulonglong2*)&Bsd[k*64 + c4]     = d0v;
        *(ulonglong2*)&Bsd[k*64 + c4 + 2] = d1v;
    }
    __syncthreads();

    ull acc2[4][4];
    #pragma unroll
    for (int p = 0; p < 4; p++)
        #pragma unroll
        for (int j = 0; j < 4; j++) acc2[p][j] = 0ull;

    #pragma unroll 5
    for (int k = 0; k < NK; k++) {
        ulonglong2 aA = *(const ulonglong2*)&As[k*128 + ty*8];
        ulonglong2 aB = *(const ulonglong2*)&As[k*128 + ty*8 + 4];
        ull av[4] = {aA.x, aA.y, aB.x, aB.y};
        ulonglong2 b0 = *(const ulonglong2*)&Bsd[k*64 + tx*4];
        ulonglong2 b1 = *(const ulonglong2*)&Bsd[k*64 + tx*4 + 2];
        ull bv[4] = {b0.x, b0.y, b1.x, b1.y};
        #pragma unroll
        for (int p = 0; p < 4; p++) {
            #pragma unroll
            for (int j = 0; j < 4; j++) ffma2(acc2[p][j], av[p], bv[j]);
        }
    }

    // store: acc2[p][j] = rows ty*8+2p/+2p+1, col col0+tx*4+j
    #pragma unroll
    for (int p = 0; p < 4; p++) {
        float2 u0 = unpack2(acc2[p][0]);
        float2 u1 = unpack2(acc2[p][1]);
        float2 u2 = unpack2(acc2[p][2]);
        float2 u3 = unpack2(acc2[p][3]);
        float4 lo = make_float4(fmaxf(u0.x,0.f), fmaxf(u1.x,0.f), fmaxf(u2.x,0.f), fmaxf(u3.x,0.f));
        float4 hi = make_float4(fmaxf(u0.y,0.f), fmaxf(u1.y,0.f), fmaxf(u2.y,0.f), fmaxf(u3.y,0.f));
        *(float4*)&g_rec1[(size_t)(row0 + ty*8 + 2*p)*NH + col0 + tx*4]     = lo;
        *(float4*)&g_rec1[(size_t)(row0 + ty*8 + 2*p + 1)*NH + col0 + tx*4] = hi;
    }
}

// ---------------- kernel 3: rec2 GEMM 128x64xK256, fused ae_loss + col sums ----------------
// grid (4, 512). micro 8x4, dup-B smem.
__global__ void __launch_bounds__(256, 4) rec2_kernel(const float* __restrict__ f,
                                                      const float* __restrict__ rv2) {
    __shared__ float As[16*128];   // [kk][row]
    __shared__ ull   Bsd[16*64];   // [kk][col] dup
    int tid = threadIdx.x;
    int tx = tid & 15, ty = tid >> 4;
    int col0 = blockIdx.x * 64;
    int row0 = blockIdx.y * 128;
    int b = row0 >> 9;
    int s00 = row0 & 511;

    ull acc2[4][4];
    #pragma unroll
    for (int p = 0; p < 4; p++)
        #pragma unroll
        for (int j = 0; j < 4; j++) acc2[p][j] = 0ull;

    for (int k0 = 0; k0 < NH; k0 += 16) {
        {
            int r = tid >> 1, half = tid & 1;
            const float* gp = g_rec1 + (size_t)(row0 + r)*NH + k0 + half*8;
            float4 t0 = *(const float4*)gp;
            float4 t1 = *(const float4*)(gp + 4);
            int kb = half*8;
            As[(kb+0)*128 + r] = t0.x; As[(kb+1)*128 + r] = t0.y;
            As[(kb+2)*128 + r] = t0.z; As[(kb+3)*128 + r] = t0.w;
            As[(kb+4)*128 + r] = t1.x; As[(kb+5)*128 + r] = t1.y;
            As[(kb+6)*128 + r] = t1.z; As[(kb+7)*128 + r] = t1.w;
        }
        {
            int kk = tid >> 4, c4 = (tid & 15) * 4;
            float4 t4 = *(const float4*)(rv2 + (size_t)(k0 + kk)*ND + col0 + c4);
            ulonglong2 d0v, d1v;
            d0v.x = pack_dup(t4.x); d0v.y = pack_dup(t4.y);
            d1v.x = pack_dup(t4.z); d1v.y = pack_dup(t4.w);
            *(ulonglong2*)&Bsd[kk*64 + c4]     = d0v;
            *(ulonglong2*)&Bsd[kk*64 + c4 + 2] = d1v;
        }
        __syncthreads();
        #pragma unroll
        for (int kk = 0; kk < 16; kk++) {
            ulonglong2 aA = *(const ulonglong2*)&As[kk*128 + ty*8];
            ulonglong2 aB = *(const ulonglong2*)&As[kk*128 + ty*8 + 4];
            ull av[4] = {aA.x, aA.y, aB.x, aB.y};
            ulonglong2 b0 = *(const ulonglong2*)&Bsd[kk*64 + tx*4];
            ulonglong2 b1 = *(const ulonglong2*)&Bsd[kk*64 + tx*4 + 2];
            ull bv[4] = {b0.x, b0.y, b1.x, b1.y};
            #pragma unroll
            for (int p = 0; p < 4; p++) {
                #pragma unroll
                for (int j = 0; j < 4; j++) ffma2(acc2[p][j], av[p], bv[j]);
            }
        }
        __syncthreads();
    }

    // epilogue: acc2[p][j] = rows ty*8+2p/+2p+1, col col0+tx*4+j
    float invn[8];
    #pragma unroll
    for (int i = 0; i < 8; i++) invn[i] = g_invnorm[row0 + ty*8 + i];
    float aeacc = 0.f;
    float* scs = As;   // 64 cols x 16 ty = 1024 floats
    #pragma unroll
    for (int j = 0; j < 4; j++) {
        int cl = tx*4 + j;
        const float* fp = f + ((size_t)(b*ND + col0 + cl))*NS + s00 + ty*8;
        float4 fa = *(const float4*)fp;
        float4 fb = *(const float4*)(fp + 4);
        float fv[8] = {fa.x, fa.y, fa.z, fa.w, fb.x, fb.y, fb.z, fb.w};
        float cs = 0.f;
        #pragma unroll
        for (int p = 0; p < 4; p++) {
            float2 c = unpack2(acc2[p][j]);
            float d0 = fv[2*p]   * invn[2*p]   - c.x;
            float d1 = fv[2*p+1] * invn[2*p+1] - c.y;
            aeacc += d0*d0 + d1*d1;
            cs += c.x + c.y;
        }
        scs[cl*16 + ty] = cs;
    }
    __syncthreads();
    if (tid < 64) {
        float ssum = 0.f;
        #pragma unroll
        for (int t = 0; t < 16; t++) ssum += scs[tid*16 + t];
        atomicAdd(&g_mean[b*ND + col0 + tid], ssum);
    }
    float* red = (float*)Bsd;
    red[tid] = aeacc;
    __syncthreads();
    for (int s = 128; s > 0; s >>= 1) { if (tid < s) red[tid] += red[tid+s]; __syncthreads(); }
    if (tid == 0) atomicAdd(&g_ae, red[0]);
}

// ---------------- final ----------------
__global__ void final_kernel(const float* __restrict__ Wc, const float* __restrict__ bc,
                             float* __restrict__ out) {
    int tid = threadIdx.x;
    int b = tid >> 1, c = tid & 1;
    float acc = 0.f;
    for (int d = 0; d < ND; d++) acc += g_mean[b*ND + d] * Wc[d*2 + c];
    out[OUT_PRED + b*2 + c] = acc * (1.0f/512.0f) + bc[c];
    if (tid == 0) {
        out[OUT_SCAL0] = 0.0f;
        out[OUT_SIM]   = -g_sim / (float)(NK * (NB/4));
        out[OUT_FAR]   = g_far;
        out[OUT_AE]    = g_ae / (float)((size_t)NROWS * ND);
    }
}

extern "C" void kernel_launch(void* const* d_in, const int* in_sizes, int n_in,
                              void* d_out, int out_size) {
    const float* f   = (const float*)d_in[0];   // [B,D,S]
    const float* tv  = (const float*)d_in[2];   // [D,K]
    const float* rv1 = (const float*)d_in[3];   // [K,H]
    const float* rv2 = (const float*)d_in[4];   // [H,D]
    const float* Wc  = (const float*)d_in[5];   // [D,NCLS]
    const float* bc  = (const float*)d_in[6];   // [NCLS]
    float* out = (float*)d_out;

    cudaFuncSetAttribute(rec1_kernel, cudaFuncAttributeMaxDynamicSharedMemorySize, REC1_SMEM);
    cudaFuncSetAttribute(topsel_kernel, cudaFuncAttributeMaxDynamicSharedMemorySize, TSEL_SMEM);

    prep_kernel<<<1, 256>>>(tv);
    topic_kernel<<<NROWS/128, 256>>>(f, out + OUT_NN);
    topsel_kernel<<<NK, 1024, TSEL_SMEM>>>();
    rec1_kernel<<<dim3(4, 512), 256, REC1_SMEM>>>(rv1);
    rec2_kernel<<<dim3(4, 512), 256>>>(f, rv2);
    final_kernel<<<1, 256>>>(Wc, bc, out);
}

// round 10
// speedup vs baseline: 1.1627x; 1.1627x over previous
#include <cuda_runtime.h>
#include <math.h>
#include <float.h>

// Problem dims
#define NB 128
#define ND 256
#define NS 512
#define NK 50
#define NH 256
#define NROWS (NB*NS)            // 65536 (b,s) rows
#define OUT_PRED 0
#define OUT_SCAL0 256
#define OUT_SIM 257
#define OUT_FAR 258
#define OUT_NN 259               // B*S*K floats
#define OUT_AE (259 + NROWS*NK)

typedef unsigned long long ull;

// ---------------- packed f32x2 helpers (FFMA2) ----------------
__device__ __forceinline__ ull pack_dup(float a) {
    ull r; asm("mov.b64 %0, {%1, %1};" : "=l"(r) : "f"(a)); return r;
}
__device__ __forceinline__ void ffma2(ull &c, ull a, ull b) {
    asm("fma.rn.f32x2 %0, %1, %2, %0;" : "+l"(c) : "l"(a), "l"(b));
}
__device__ __forceinline__ float2 unpack2(ull v) {
    float2 f; asm("mov.b64 {%0, %1}, %2;" : "=f"(f.x), "=f"(f.y) : "l"(v)); return f;
}

// ---------------- device scratch ----------------
__device__ __align__(16) float g_tvn[ND*NK];
__device__ __align__(16) float g_tvnp[ND*64];     // padded [D][64]
__device__ __align__(16) float g_invnorm[NROWS];
__device__ __align__(16) float g_tpnT[NK*NROWS];  // [K][B*S]
__device__ __align__(16) float g_nnT[NK*NROWS];   // nn transposed [K][B*S]
__device__ __align__(16) float g_rec1[NROWS*NH];
__device__ __align__(16) float g_mean[NB*ND];
__device__ float g_ae;
__device__ float g_sim;
__device__ float g_far;

// ---------------- kernel 0: prep ----------------
__global__ void prep_kernel(const float* __restrict__ tv) {
    __shared__ float inv[64];
    __shared__ float red[256];
    int tid = threadIdx.x;
    if (tid < NK) {
        float ss = 0.f;
        for (int d = 0; d < ND; d++) { float v = tv[d*NK + tid]; ss += v*v; }
        inv[tid] = 1.0f / fmaxf(sqrtf(ss), 1e-12f);
    }
    __syncthreads();
    for (int i = tid; i < ND*NK; i += 256) g_tvn[i] = tv[i] * inv[i % NK];
    for (int i = tid; i < NB*ND; i += 256) g_mean[i] = 0.f;
    if (tid == 0) { g_ae = 0.f; g_sim = 0.f; }
    __syncthreads();
    for (int i = tid; i < ND*64; i += 256) {
        int d = i >> 6, k = i & 63;
        g_tvnp[i] = (k < NK) ? g_tvn[d*NK + k] : 0.f;
    }
    float acc = 0.f;
    for (int p = tid; p < NK*NK; p += 256) {
        int i = p / NK, j = p % NK;
        float ds = 0.f;
        for (int d = 0; d < ND; d++) ds += g_tvn[d*NK + i] * g_tvn[d*NK + j];
        acc += ds - ((i == j) ? 1.0f : 0.0f);
    }
    red[tid] = acc; __syncthreads();
    for (int s = 128; s > 0; s >>= 1) { if (tid < s) red[tid] += red[tid+s]; __syncthreads(); }
    if (tid == 0) g_far = red[0] / (float)(NK*NK);
}

// ---------------- kernel 1: topic GEMM 256x64xK256 + fused norm/mask/nn ----------------
// 256 thr: tx = tid&7 (cols tx*8..+7), ty = tid>>3 (rows ty*8..+7 of 256). micro 8x8.
// A stored DUPLICATED (ull), B natural col-pairs.
__global__ void __launch_bounds__(256) topic_kernel(const float* __restrict__ f,
                                                    float* __restrict__ out_nn) {
    __shared__ ull   Asd[16*256];         // [kk][row] dup f32x2 (32 KB)
    __shared__ float Bs[16*64];           // [kk][col] (4 KB)
    __shared__ float spart[256*8];
    __shared__ float inv_s[256];
    __shared__ float den_s[256];

    int tid = threadIdx.x;
    int tx = tid & 7, ty = tid >> 3;
    int row0 = blockIdx.x * 256;
    int b = row0 >> 9;
    int s00 = row0 & 511;

    ull acc2[8][4];
    #pragma unroll
    for (int i = 0; i < 8; i++)
        #pragma unroll
        for (int j = 0; j < 4; j++) acc2[i][j] = 0ull;
    float ssq[8];
    #pragma unroll
    for (int i = 0; i < 8; i++) ssq[i] = 0.f;

    for (int d0 = 0; d0 < ND; d0 += 16) {
        #pragma unroll
        for (int it = 0; it < 4; it++) {
            int v = tid + it*256;
            int kk = v >> 6, r4 = (v & 63) * 4;
            float4 t4 = *(const float4*)(f + ((size_t)(b*ND + d0 + kk))*NS + s00 + r4);
            Asd[kk*256 + r4 + 0] = pack_dup(t4.x);
            Asd[kk*256 + r4 + 1] = pack_dup(t4.y);
            Asd[kk*256 + r4 + 2] = pack_dup(t4.z);
            Asd[kk*256 + r4 + 3] = pack_dup(t4.w);
        }
        {
            int kk = tid >> 4, j4 = (tid & 15) * 4;
            *(float4*)&Bs[kk*64 + j4] = *(const float4*)&g_tvnp[(d0 + kk)*64 + j4];
        }
        __syncthreads();
        #pragma unroll
        for (int kk = 0; kk < 16; kk++) {
            ull av[8];
            #pragma unroll
            for (int q = 0; q < 4; q++) {
                ulonglong2 t = *(const ulonglong2*)&Asd[kk*256 + ty*8 + q*2];
                av[q*2] = t.x; av[q*2+1] = t.y;
            }
            ulonglong2 b01 = *(const ulonglong2*)&Bs[kk*64 + tx*8];
            ulonglong2 b23 = *(const ulonglong2*)&Bs[kk*64 + tx*8 + 4];
            ull bv[4] = {b01.x, b01.y, b23.x, b23.y};
            #pragma unroll
            for (int i = 0; i < 8; i++) {
                #pragma unroll
                for (int j = 0; j < 4; j++) ffma2(acc2[i][j], av[i], bv[j]);
            }
            if (tx == 0) {
                #pragma unroll
                for (int i = 0; i < 8; i++) {
                    float a = unpack2(av[i]).x;
                    ssq[i] += a*a;
                }
            }
        }
        __syncthreads();
    }

    if (tx == 0) {
        #pragma unroll
        for (int i = 0; i < 8; i++) {
            float iv = 1.0f / fmaxf(sqrtf(ssq[i]), 1e-12f);
            inv_s[ty*8 + i] = iv;
            g_invnorm[row0 + ty*8 + i] = iv;
        }
    }
    __syncthreads();

    // acc2[i][j] = row ty*8+i, cols (tx*8+2j, tx*8+2j+1)
    float tp[8][8], amv[8][8], iv[8];
    #pragma unroll
    for (int i = 0; i < 8; i++) iv[i] = inv_s[ty*8 + i];
    #pragma unroll
    for (int i = 0; i < 8; i++) {
        #pragma unroll
        for (int j = 0; j < 4; j++) {
            float2 c = unpack2(acc2[i][j]);
            tp[i][2*j]   = c.x;
            tp[i][2*j+1] = c.y;
        }
        float psum = 0.f;
        #pragma unroll
        for (int j = 0; j < 8; j++) {
            float t = tp[i][j] * iv[i];
            float am = (t > 0.3f) ? tp[i][j] : 0.f;
            amv[i][j] = am;
            psum += am;                 // pad cols exactly 0
        }
        spart[(ty*8 + i)*8 + tx] = psum;
    }
    __syncthreads();
    {
        float s = 0.f;
        #pragma unroll
        for (int t = 0; t < 8; t++) s += spart[tid*8 + t];
        den_s[tid] = 1.0f / ((s + 0.001f) + 1e-8f);
    }
    __syncthreads();

    #pragma unroll
    for (int i = 0; i < 8; i++) {
        int row = row0 + ty*8 + i;
        float den = den_s[ty*8 + i];
        #pragma unroll
        for (int j = 0; j < 8; j++) {
            int k = tx*8 + j;
            if (k < NK) {
                float v = amv[i][j] * den;
                out_nn[(size_t)row*NK + k] = v;
                g_nnT[(size_t)k*NROWS + row] = v;
                g_tpnT[(size_t)k*NROWS + row] = tp[i][j] * iv[i];
            }
        }
    }
}

// ---------------- radix top-32 select per concept ----------------
#define TSEL_CAP 16384
#define TSEL_SMEM ((4096 + 1024 + TSEL_CAP + 1024 + 1024) * 4)
__global__ void __launch_bounds__(1024) topsel_kernel() {
    extern __shared__ unsigned smu[];
    unsigned* hist  = smu;
    unsigned* sscan = smu + 4096;
    float*    buf   = (float*)(smu + 5120);
    float*    red   = buf + TSEL_CAP;
    int*      ridx  = (int*)(red + 1024);
    __shared__ unsigned s_cnt, s_T, s_cntAbove, s_g;
    __shared__ float s_above;

    int tid = threadIdx.x;
    int k = blockIdx.x;
    const float* src = g_tpnT + (size_t)k * NROWS;

    for (int i = tid; i < 4096; i += 1024) hist[i] = 0u;
    if (tid == 0) s_cnt = 0u;
    __syncthreads();

    for (int i = tid; i < NROWS; i += 1024) {
        unsigned u = __float_as_uint(src[i]);
        u = (u & 0x80000000u) ? ~u : (u | 0x80000000u);
        atomicAdd(&hist[u >> 20], 1u);
    }
    __syncthreads();

    unsigned gsum = hist[4*tid] + hist[4*tid+1] + hist[4*tid+2] + hist[4*tid+3];
    sscan[tid] = gsum;
    __syncthreads();
    for (int off = 1; off < 1024; off <<= 1) {
        unsigned add = (tid + off < 1024) ? sscan[tid + off] : 0u;
        __syncthreads();
        sscan[tid] += add;
        __syncthreads();
    }
    {
        unsigned Sh = sscan[tid];
        unsigned Sn = (tid < 1023) ? sscan[tid + 1] : 0u;
        if (Sh >= 32u && Sn < 32u) s_g = (unsigned)tid;
    }
    __syncthreads();
    if (tid == 0) {
        int g = (int)s_g;
        unsigned cum = (g < 1023) ? sscan[g + 1] : 0u;
        for (int bb = 4*g + 3; bb >= 4*g; bb--) {
            unsigned h = hist[bb];
            if (cum + h >= 32u) { s_T = (unsigned)bb; s_cntAbove = cum; break; }
            cum += h;
        }
    }
    __syncthreads();
    unsigned T = s_T;

    float sumAbove = 0.f;
    for (int i = tid; i < NROWS; i += 1024) {
        float v = src[i];
        unsigned u = __float_as_uint(v);
        u = (u & 0x80000000u) ? ~u : (u | 0x80000000u);
        unsigned bn = u >> 20;
        if (bn > T) sumAbove += v;
        else if (bn == T) {
            unsigned p = atomicAdd(&s_cnt, 1u);
            if (p < TSEL_CAP) buf[p] = v;
        }
    }
    red[tid] = sumAbove;
    __syncthreads();
    for (int s = 512; s > 0; s >>= 1) { if (tid < s) red[tid] += red[tid+s]; __syncthreads(); }
    if (tid == 0) s_above = red[0];
    __syncthreads();

    int n = (int)min(s_cnt, (unsigned)TSEL_CAP);
    int need = 32 - (int)s_cntAbove;
    float picked = 0.f;
    for (int it = 0; it < need; it++) {
        float lm = -FLT_MAX; int li = 0;
        for (int j = tid; j < n; j += 1024) { float x = buf[j]; if (x > lm) { lm = x; li = j; } }
        red[tid] = lm; ridx[tid] = li;
        __syncthreads();
        for (int s = 512; s > 0; s >>= 1) {
            if (tid < s && red[tid+s] > red[tid]) { red[tid] = red[tid+s]; ridx[tid] = ridx[tid+s]; }
            __syncthreads();
        }
        if (tid == 0) { picked += red[0]; buf[ridx[0]] = -FLT_MAX; }
        __syncthreads();
    }
    if (tid == 0) atomicAdd(&g_sim, s_above + picked);
}

// ---------------- kernel 2: rec1 GEMM 128x128xK50, relu ----------------
// grid (2, 512). dyn smem: Asd[50*128] ull | Bs[50*128] f. micro 8x8, dup-A.
#define REC1_SMEM (NK*128*8 + NK*128*4)
__global__ void __launch_bounds__(256) rec1_kernel(const float* __restrict__ rv1) {
    extern __shared__ float sm[];
    ull*   Asd = (ull*)sm;                 // [k][row] dup
    float* Bs  = sm + NK*128*2;            // [k][col]
    int tid = threadIdx.x;
    int tx = tid & 15, ty = tid >> 4;
    int col0 = blockIdx.x * 128;
    int row0 = blockIdx.y * 128;

    for (int v = tid; v < 1600; v += 256) {
        int k = v >> 5, r4 = (v & 31) * 4;
        float4 t4 = *(const float4*)&g_nnT[(size_t)k*NROWS + row0 + r4];
        Asd[k*128 + r4 + 0] = pack_dup(t4.x);
        Asd[k*128 + r4 + 1] = pack_dup(t4.y);
        Asd[k*128 + r4 + 2] = pack_dup(t4.z);
        Asd[k*128 + r4 + 3] = pack_dup(t4.w);
    }
    for (int v = tid; v < 1600; v += 256) {
        int k = v >> 5, j4 = (v & 31) * 4;
        *(float4*)&Bs[k*128 + j4] = *(const float4*)(rv1 + k*NH + col0 + j4);
    }
    __syncthreads();

    ull acc2[8][4];
    #pragma unroll
    for (int i = 0; i < 8; i++)
        #pragma unroll
        for (int j = 0; j < 4; j++) acc2[i][j] = 0ull;

    #pragma unroll 10
    for (int k = 0; k < NK; k++) {
        ull av[8];
        #pragma unroll
        for (int q = 0; q < 4; q++) {
            ulonglong2 t = *(const ulonglong2*)&Asd[k*128 + ty*8 + q*2];
            av[q*2] = t.x; av[q*2+1] = t.y;
        }
        ulonglong2 b01 = *(const ulonglong2*)&Bs[k*128 + tx*8];
        ulonglong2 b23 = *(const ulonglong2*)&Bs[k*128 + tx*8 + 4];
        ull bv[4] = {b01.x, b01.y, b23.x, b23.y};
        #pragma unroll
        for (int i = 0; i < 8; i++) {
            #pragma unroll
            for (int j = 0; j < 4; j++) ffma2(acc2[i][j], av[i], bv[j]);
        }
    }

    // acc2[i][j] = row ty*8+i, cols (tx*8+2j, +2j+1): contiguous 8 cols per row
    #pragma unroll
    for (int i = 0; i < 8; i++) {
        int row = row0 + ty*8 + i;
        float o[8];
        #pragma unroll
        for (int j = 0; j < 4; j++) {
            float2 c = unpack2(acc2[i][j]);
            o[2*j]   = fmaxf(c.x, 0.f);
            o[2*j+1] = fmaxf(c.y, 0.f);
        }
        *(float4*)&g_rec1[(size_t)row*NH + col0 + tx*8]     = *(float4*)&o[0];
        *(float4*)&g_rec1[(size_t)row*NH + col0 + tx*8 + 4] = *(float4*)&o[4];
    }
}

// ---------------- kernel 3: rec2 GEMM 128x128xK256, fused ae_loss + col sums ----------------
// grid (2, 512). micro 8x8, dup-A smem, natural-pair B.
__global__ void __launch_bounds__(256) rec2_kernel(const float* __restrict__ f,
                                                   const float* __restrict__ rv2) {
    __shared__ ull   Asd[16*128];  // [kk][row] dup (16 KB)
    __shared__ float Bs[16*128];   // [kk][col] (8 KB)
    int tid = threadIdx.x;
    int tx = tid & 15, ty = tid >> 4;
    int col0 = blockIdx.x * 128;
    int row0 = blockIdx.y * 128;
    int b = row0 >> 9;
    int s00 = row0 & 511;

    ull acc2[8][4];
    #pragma unroll
    for (int i = 0; i < 8; i++)
        #pragma unroll
        for (int j = 0; j < 4; j++) acc2[i][j] = 0ull;

    for (int k0 = 0; k0 < NH; k0 += 16) {
        {
            int r = tid >> 1, half = tid & 1;
            const float* gp = g_rec1 + (size_t)(row0 + r)*NH + k0 + half*8;
            float4 t0 = *(const float4*)gp;
            float4 t1 = *(const float4*)(gp + 4);
            int kb = half*8;
            Asd[(kb+0)*128 + r] = pack_dup(t0.x);
            Asd[(kb+1)*128 + r] = pack_dup(t0.y);
            Asd[(kb+2)*128 + r] = pack_dup(t0.z);
            Asd[(kb+3)*128 + r] = pack_dup(t0.w);
            Asd[(kb+4)*128 + r] = pack_dup(t1.x);
            Asd[(kb+5)*128 + r] = pack_dup(t1.y);
            Asd[(kb+6)*128 + r] = pack_dup(t1.z);
            Asd[(kb+7)*128 + r] = pack_dup(t1.w);
        }
        #pragma unroll
        for (int it = 0; it < 2; it++) {
            int v = tid + it*256;
            int kk = v >> 5, c4 = (v & 31) * 4;
            *(float4*)&Bs[kk*128 + c4] = *(const float4*)(rv2 + (size_t)(k0 + kk)*ND + col0 + c4);
        }
        __syncthreads();
        #pragma unroll
        for (int kk = 0; kk < 16; kk++) {
            ull av[8];
            #pragma unroll
            for (int q = 0; q < 4; q++) {
                ulonglong2 t = *(const ulonglong2*)&Asd[kk*128 + ty*8 + q*2];
                av[q*2] = t.x; av[q*2+1] = t.y;
            }
            ulonglong2 b01 = *(const ulonglong2*)&Bs[kk*128 + tx*8];
            ulonglong2 b23 = *(const ulonglong2*)&Bs[kk*128 + tx*8 + 4];
            ull bv[4] = {b01.x, b01.y, b23.x, b23.y};
            #pragma unroll
            for (int i = 0; i < 8; i++) {
                #pragma unroll
                for (int j = 0; j < 4; j++) ffma2(acc2[i][j], av[i], bv[j]);
            }
        }
        __syncthreads();
    }

    // epilogue: acc2[i][j] = row ty*8+i, cols col0 + tx*8 + 2j, +2j+1
    float invn[8];
    #pragma unroll
    for (int i = 0; i < 8; i++) invn[i] = g_invnorm[row0 + ty*8 + i];
    float aeacc = 0.f;
    float* scs = (float*)Asd;   // 128 cols x 16 ty = 2048 floats
    #pragma unroll
    for (int jj = 0; jj < 4; jj++) {
        int cl = tx*8 + 2*jj;
        int c0 = col0 + cl;
        float cs0 = 0.f, cs1 = 0.f;
        const float* fp0 = f + ((size_t)(b*ND + c0))*NS + s00 + ty*8;
        const float* fp1 = fp0 + NS;
        #pragma unroll
        for (int i = 0; i < 8; i++) {
            float2 c = unpack2(acc2[i][jj]);
            float d0 = fp0[i] * invn[i] - c.x;
            float d1 = fp1[i] * invn[i] - c.y;
            aeacc += d0*d0 + d1*d1;
            cs0 += c.x; cs1 += c.y;
        }
        scs[cl*16 + ty]     = cs0;
        scs[(cl+1)*16 + ty] = cs1;
    }
    __syncthreads();
    if (tid < 128) {
        float ssum = 0.f;
        #pragma unroll
        for (int t = 0; t < 16; t++) ssum += scs[tid*16 + t];
        atomicAdd(&g_mean[b*ND + col0 + tid], ssum);
    }
    float* red = Bs;
    red[tid] = aeacc;
    __syncthreads();
    for (int s = 128; s > 0; s >>= 1) { if (tid < s) red[tid] += red[tid+s]; __syncthreads(); }
    if (tid == 0) atomicAdd(&g_ae, red[0]);
}

// ---------------- final ----------------
__global__ void final_kernel(const float* __restrict__ Wc, const float* __restrict__ bc,
                             float* __restrict__ out) {
    int tid = threadIdx.x;
    int b = tid >> 1, c = tid & 1;
    float acc = 0.f;
    for (int d = 0; d < ND; d++) acc += g_mean[b*ND + d] * Wc[d*2 + c];
    out[OUT_PRED + b*2 + c] = acc * (1.0f/512.0f) + bc[c];
    if (tid == 0) {
        out[OUT_SCAL0] = 0.0f;
        out[OUT_SIM]   = -g_sim / (float)(NK * (NB/4));
        out[OUT_FAR]   = g_far;
        out[OUT_AE]    = g_ae / (float)((size_t)NROWS * ND);
    }
}

extern "C" void kernel_launch(void* const* d_in, const int* in_sizes, int n_in,
                              void* d_out, int out_size) {
    const float* f   = (const float*)d_in[0];   // [B,D,S]
    const float* tv  = (const float*)d_in[2];   // [D,K]
    const float* rv1 = (const float*)d_in[3];   // [K,H]
    const float* rv2 = (const float*)d_in[4];   // [H,D]
    const float* Wc  = (const float*)d_in[5];   // [D,NCLS]
    const float* bc  = (const float*)d_in[6];   // [NCLS]
    float* out = (float*)d_out;

    cudaFuncSetAttribute(rec1_kernel, cudaFuncAttributeMaxDynamicSharedMemorySize, REC1_SMEM);
    cudaFuncSetAttribute(topsel_kernel, cudaFuncAttributeMaxDynamicSharedMemorySize, TSEL_SMEM);

    prep_kernel<<<1, 256>>>(tv);
    topic_kernel<<<NROWS/256, 256>>>(f, out + OUT_NN);
    topsel_kernel<<<NK, 1024, TSEL_SMEM>>>();
    rec1_kernel<<<dim3(2, 512), 256, REC1_SMEM>>>(rv1);
    rec2_kernel<<<dim3(2, 512), 256>>>(f, rv2);
    final_kernel<<<1, 256>>>(Wc, bc, out);
}

// round 14
// speedup vs baseline: 1.3991x; 1.2033x over previous
#include <stdint.h>
#include <cstdint>
#include <cuda_runtime.h>
#include <cuda_bf16.h>
#include <math.h>
#include <float.h>

// Problem dims
#define NB 128
#define ND 256
#define NS 512
#define NK 50
#define NH 256
#define NROWS (NB*NS)            // 65536 (b,s) rows
#define OUT_PRED 0
#define OUT_SCAL0 256
#define OUT_SIM 257
#define OUT_FAR 258
#define OUT_NN 259               // B*S*K floats
#define OUT_AE (259 + NROWS*NK)

typedef unsigned long long ull;

// ---------------- packed f32x2 helpers (FFMA2) ----------------
__device__ __forceinline__ ull pack_dup(float a) {
    ull r; asm("mov.b64 %0, {%1, %1};" : "=l"(r) : "f"(a)); return r;
}
__device__ __forceinline__ void ffma2(ull &c, ull a, ull b) {
    asm("fma.rn.f32x2 %0, %1, %2, %0;" : "+l"(c) : "l"(a), "l"(b));
}
__device__ __forceinline__ float2 unpack2(ull v) {
    float2 f; asm("mov.b64 {%0, %1}, %2;" : "=f"(f.x), "=f"(f.y) : "l"(v)); return f;
}

// ---------------- warp MMA m16n8k16 bf16 (baseline PTX, HMMA on tensor pipe) ----------------
__device__ __forceinline__ void mma16816(float* c, const uint32_t* a, const uint32_t* b) {
    asm volatile("mma.sync.aligned.m16n8k16.row.col.f32.bf16.bf16.f32 "
        "{%0,%1,%2,%3}, {%4,%5,%6,%7}, {%8,%9}, {%0,%1,%2,%3};"
        : "+f"(c[0]), "+f"(c[1]), "+f"(c[2]), "+f"(c[3])
        : "r"(a[0]), "r"(a[1]), "r"(a[2]), "r"(a[3]), "r"(b[0]), "r"(b[1]));
}

// ---------------- bf16 split helpers ----------------
__device__ __forceinline__ void split_bf16(float v, unsigned short &h, unsigned short &l) {
    __nv_bfloat16 hb = __float2bfloat16(v);
    float r = v - __bfloat162float(hb);
    __nv_bfloat16 lb = __float2bfloat16(r);
    h = *(unsigned short*)&hb;
    l = *(unsigned short*)&lb;
}

// ---------------- device scratch ----------------
__device__ __align__(16) float g_tvn[ND*NK];
__device__ __align__(16) float g_tvnp[ND*64];     // padded [D][64]
__device__ __align__(16) float g_invnorm[NROWS];
__device__ __align__(16) float g_tpnT[NK*NROWS];  // [K][B*S]
__device__ __align__(16) float g_nnT[NK*NROWS];   // nn transposed [K][B*S]
__device__ __align__(16) unsigned short g_rec1h[NROWS*NH];  // bf16 hi of relu(nn@rv1)
__device__ __align__(16) unsigned short g_rec1l[NROWS*NH];  // bf16 lo
__device__ __align__(16) unsigned short g_rv2hT[ND*NH];     // bf16 hi of rv2^T  [n][k]
__device__ __align__(16) unsigned short g_rv2lT[ND*NH];     // bf16 lo
__device__ __align__(16) float g_h1sum[NB*NH];    // sum_s rec1[b,s,h]
__device__ __align__(16) float g_mean[NB*ND];
__device__ float g_ae;
__device__ float g_sim;
__device__ float g_far;

// ---------------- kernel 0: prep ----------------
__global__ void prep_kernel(const float* __restrict__ tv) {
    __shared__ float inv[64];
    __shared__ float red[256];
    int tid = threadIdx.x;
    if (tid < NK) {
        float ss = 0.f;
        for (int d = 0; d < ND; d++) { float v = tv[d*NK + tid]; ss += v*v; }
        inv[tid] = 1.0f / fmaxf(sqrtf(ss), 1e-12f);
    }
    __syncthreads();
    for (int i = tid; i < ND*NK; i += 256) g_tvn[i] = tv[i] * inv[i % NK];
    for (int i = tid; i < NB*NH; i += 256) g_h1sum[i] = 0.f;
    if (tid == 0) { g_ae = 0.f; g_sim = 0.f; }
    __syncthreads();
    for (int i = tid; i < ND*64; i += 256) {
        int d = i >> 6, k = i & 63;
        g_tvnp[i] = (k < NK) ? g_tvn[d*NK + k] : 0.f;
    }
    float acc = 0.f;
    for (int p = tid; p < NK*NK; p += 256) {
        int i = p / NK, j = p % NK;
        float ds = 0.f;
        for (int d = 0; d < ND; d++) ds += g_tvn[d*NK + i] * g_tvn[d*NK + j];
        acc += ds - ((i == j) ? 1.0f : 0.0f);
    }
    red[tid] = acc; __syncthreads();
    for (int s = 128; s > 0; s >>= 1) { if (tid < s) red[tid] += red[tid+s]; __syncthreads(); }
    if (tid == 0) g_far = red[0] / (float)(NK*NK);
}

// ---------------- convert rv2 to transposed bf16 hi/lo ----------------
__global__ void convrv2_kernel(const float* __restrict__ rv2) {
    int k = blockIdx.x, n = threadIdx.x;
    float v = rv2[k*ND + n];
    unsigned short h, l;
    split_bf16(v, h, l);
    g_rv2hT[n*NH + k] = h;
    g_rv2lT[n*NH + k] = l;
}

// ---------------- kernel 1: topic GEMM 256x64xK256 + fused norm/mask/nn (R6) ----------------
__global__ void __launch_bounds__(256) topic_kernel(const float* __restrict__ f,
                                                    float* __restrict__ out_nn) {
    __shared__ float As[16*256];
    __shared__ float Bs[16*64];
    __shared__ float spart[256*8];
    __shared__ float inv_s[256];
    __shared__ float den_s[256];

    int tid = threadIdx.x;
    int tx = tid & 7, ty = tid >> 3;
    int row0 = blockIdx.x * 256;
    int b = row0 >> 9;
    int s00 = row0 & 511;

    ull acc2[8][4];
    #pragma unroll
    for (int i = 0; i < 8; i++)
        #pragma unroll
        for (int j = 0; j < 4; j++) acc2[i][j] = 0ull;
    float ssq[8];
    #pragma unroll
    for (int i = 0; i < 8; i++) ssq[i] = 0.f;

    for (int d0 = 0; d0 < ND; d0 += 16) {
        #pragma unroll
        for (int it = 0; it < 4; it++) {
            int v = tid + it*256;
            int kk = v >> 6, r4 = (v & 63) * 4;
            float4 t4 = *(const float4*)(f + ((size_t)(b*ND + d0 + kk))*NS + s00 + r4);
            *(float4*)&As[kk*256 + r4] = t4;
        }
        {
            int kk = tid >> 4, j4 = (tid & 15) * 4;
            *(float4*)&Bs[kk*64 + j4] = *(const float4*)&g_tvnp[(d0 + kk)*64 + j4];
        }
        __syncthreads();
        float a[8], an[8];
        ull bb[4], bn[4];
        {
            *(float4*)&a[0] = *(const float4*)&As[ty*8];
            *(float4*)&a[4] = *(const float4*)&As[ty*8 + 4];
            ulonglong2 q0 = *(const ulonglong2*)&Bs[tx*4];
            ulonglong2 q1 = *(const ulonglong2*)&Bs[32 + tx*4];
            bb[0]=q0.x; bb[1]=q0.y; bb[2]=q1.x; bb[3]=q1.y;
        }
        #pragma unroll
        for (int kk = 0; kk < 16; kk++) {
            if (kk < 15) {
                *(float4*)&an[0] = *(const float4*)&As[(kk+1)*256 + ty*8];
                *(float4*)&an[4] = *(const float4*)&As[(kk+1)*256 + ty*8 + 4];
                ulonglong2 q0 = *(const ulonglong2*)&Bs[(kk+1)*64 + tx*4];
                ulonglong2 q1 = *(const ulonglong2*)&Bs[(kk+1)*64 + 32 + tx*4];
                bn[0]=q0.x; bn[1]=q0.y; bn[2]=q1.x; bn[3]=q1.y;
            }
            #pragma unroll
            for (int i = 0; i < 8; i++) {
                ull ad = pack_dup(a[i]);
                #pragma unroll
                for (int j = 0; j < 4; j++) ffma2(acc2[i][j], ad, bb[j]);
            }
            if (tx == 0) {
                #pragma unroll
                for (int i = 0; i < 8; i++) ssq[i] += a[i]*a[i];
            }
            if (kk < 15) {
                #pragma unroll
                for (int i = 0; i < 8; i++) a[i] = an[i];
                #pragma unroll
                for (int j = 0; j < 4; j++) bb[j] = bn[j];
            }
        }
        __syncthreads();
    }

    if (tx == 0) {
        #pragma unroll
        for (int i = 0; i < 8; i++) {
            float iv = 1.0f / fmaxf(sqrtf(ssq[i]), 1e-12f);
            inv_s[ty*8 + i] = iv;
            g_invnorm[row0 + ty*8 + i] = iv;
        }
    }
    __syncthreads();

    float tp[8][8], amv[8][8], iv[8];
    #pragma unroll
    for (int i = 0; i < 8; i++) iv[i] = inv_s[ty*8 + i];
    #pragma unroll
    for (int i = 0; i < 8; i++) {
        #pragma unroll
        for (int j = 0; j < 4; j++) {
            float2 c = unpack2(acc2[i][j]);
            tp[i][j*2] = c.x; tp[i][j*2+1] = c.y;
        }
        float psum = 0.f;
        #pragma unroll
        for (int j = 0; j < 8; j++) {
            float t = tp[i][j] * iv[i];
            float am = (t > 0.3f) ? tp[i][j] : 0.f;
            amv[i][j] = am;
            psum += am;
        }
        spart[(ty*8 + i)*8 + tx] = psum;
    }
    __syncthreads();
    {
        float s = 0.f;
        #pragma unroll
        for (int t = 0; t < 8; t++) s += spart[tid*8 + t];
        den_s[tid] = 1.0f / ((s + 0.001f) + 1e-8f);
    }
    __syncthreads();

    #pragma unroll
    for (int i = 0; i < 8; i++) {
        int row = row0 + ty*8 + i;
        float den = den_s[ty*8 + i];
        #pragma unroll
        for (int j = 0; j < 8; j++) {
            int k = ((j >= 4) ? 32 : 0) + tx*4 + (j & 3);
            if (k < NK) {
                float v = amv[i][j] * den;
                out_nn[(size_t)row*NK + k] = v;
                g_nnT[(size_t)k*NROWS + row] = v;
                g_tpnT[(size_t)k*NROWS + row] = tp[i][j] * iv[i];
            }
        }
    }
}

// ---------------- radix top-32 select per concept ----------------
#define TSEL_CAP 16384
#define TSEL_SMEM ((4096 + 1024 + TSEL_CAP + 1024 + 1024) * 4)
__global__ void __launch_bounds__(1024) topsel_kernel() {
    extern __shared__ unsigned smu[];
    unsigned* hist  = smu;
    unsigned* sscan = smu + 4096;
    float*    buf   = (float*)(smu + 5120);
    float*    red   = buf + TSEL_CAP;
    int*      ridx  = (int*)(red + 1024);
    __shared__ unsigned s_cnt, s_T, s_cntAbove, s_g;
    __shared__ float s_above;

    int tid = threadIdx.x;
    int k = blockIdx.x;
    const float* src = g_tpnT + (size_t)k * NROWS;

    for (int i = tid; i < 4096; i += 1024) hist[i] = 0u;
    if (tid == 0) s_cnt = 0u;
    __syncthreads();

    for (int i = tid; i < NROWS; i += 1024) {
        unsigned u = __float_as_uint(src[i]);
        u = (u & 0x80000000u) ? ~u : (u | 0x80000000u);
        atomicAdd(&hist[u >> 20], 1u);
    }
    __syncthreads();

    unsigned gsum = hist[4*tid] + hist[4*tid+1] + hist[4*tid+2] + hist[4*tid+3];
    sscan[tid] = gsum;
    __syncthreads();
    for (int off = 1; off < 1024; off <<= 1) {
        unsigned add = (tid + off < 1024) ? sscan[tid + off] : 0u;
        __syncthreads();
        sscan[tid] += add;
        __syncthreads();
    }
    {
        unsigned Sh = sscan[tid];
        unsigned Sn = (tid < 1023) ? sscan[tid + 1] : 0u;
        if (Sh >= 32u && Sn < 32u) s_g = (unsigned)tid;
    }
    __syncthreads();
    if (tid == 0) {
        int g = (int)s_g;
        unsigned cum = (g < 1023) ? sscan[g + 1] : 0u;
        for (int bb = 4*g + 3; bb >= 4*g; bb--) {
            unsigned h = hist[bb];
            if (cum + h >= 32u) { s_T = (unsigned)bb; s_cntAbove = cum; break; }
            cum += h;
        }
    }
    __syncthreads();
    unsigned T = s_T;

    float sumAbove = 0.f;
    for (int i = tid; i < NROWS; i += 1024) {
        float v = src[i];
        unsigned u = __float_as_uint(v);
        u = (u & 0x80000000u) ? ~u : (u | 0x80000000u);
        unsigned bn = u >> 20;
        if (bn > T) sumAbove += v;
        else if (bn == T) {
            unsigned p = atomicAdd(&s_cnt, 1u);
            if (p < TSEL_CAP) buf[p] = v;
        }
    }
    red[tid] = sumAbove;
    __syncthreads();
    for (int s = 512; s > 0; s >>= 1) { if (tid < s) red[tid] += red[tid+s]; __syncthreads(); }
    if (tid == 0) s_above = red[0];
    __syncthreads();

    int n = (int)min(s_cnt, (unsigned)TSEL_CAP);
    int need = 32 - (int)s_cntAbove;
    float picked = 0.f;
    for (int it = 0; it < need; it++) {
        float lm = -FLT_MAX; int li = 0;
        for (int j = tid; j < n; j += 1024) { float x = buf[j]; if (x > lm) { lm = x; li = j; } }
        red[tid] = lm; ridx[tid] = li;
        __syncthreads();
        for (int s = 512; s > 0; s >>= 1) {
            if (tid < s && red[tid+s] > red[tid]) { red[tid] = red[tid+s]; ridx[tid] = ridx[tid+s]; }
            __syncthreads();
        }
        if (tid == 0) { picked += red[0]; buf[ridx[0]] = -FLT_MAX; }
        __syncthreads();
    }
    if (tid == 0) atomicAdd(&g_sim, s_above + picked);
}

// ---------------- kernel 2: rec1 GEMM 128x128xK50, relu -> bf16 hi/lo + rowsums ----------------
#define REC1_SMEM (2 * NK * 128 * 4)
__global__ void __launch_bounds__(256) rec1_kernel(const float* __restrict__ rv1) {
    extern __shared__ float sm[];
    float* As = sm;            // [k][row] 50*128
    float* Bs = sm + NK*128;   // [k][col] 50*128
    int tid = threadIdx.x;
    int tx = tid & 15, ty = tid >> 4;
    int col0 = blockIdx.x * 128;
    int row0 = blockIdx.y * 128;
    int b = row0 >> 9;

    for (int v = tid; v < 1600; v += 256) {
        int k = v >> 5, r4 = (v & 31) * 4;
        *(float4*)&As[k*128 + r4] = *(const float4*)&g_nnT[(size_t)k*NROWS + row0 + r4];
    }
    for (int v = tid; v < 1600; v += 256) {
        int k = v >> 5, j4 = (v & 31) * 4;
        *(float4*)&Bs[k*128 + j4] = *(const float4*)(rv1 + k*NH + col0 + j4);
    }
    __syncthreads();

    ull acc2[8][4];
    #pragma unroll
    for (int i = 0; i < 8; i++)
        #pragma unroll
        for (int j = 0; j < 4; j++) acc2[i][j] = 0ull;

    float a[8], an[8];
    ull bb[4], bn[4];
    {
        *(float4*)&a[0] = *(const float4*)&As[ty*8];
        *(float4*)&a[4] = *(const float4*)&As[ty*8 + 4];
        ulonglong2 q0 = *(const ulonglong2*)&Bs[tx*4];
        ulonglong2 q1 = *(const ulonglong2*)&Bs[64 + tx*4];
        bb[0]=q0.x; bb[1]=q0.y; bb[2]=q1.x; bb[3]=q1.y;
    }
    #pragma unroll 2
    for (int k = 0; k < NK; k++) {
        if (k < NK-1) {
            *(float4*)&an[0] = *(const float4*)&As[(k+1)*128 + ty*8];
            *(float4*)&an[4] = *(const float4*)&As[(k+1)*128 + ty*8 + 4];
            ulonglong2 q0 = *(const ulonglong2*)&Bs[(k+1)*128 + tx*4];
            ulonglong2 q1 = *(const ulonglong2*)&Bs[(k+1)*128 + 64 + tx*4];
            bn[0]=q0.x; bn[1]=q0.y; bn[2]=q1.x; bn[3]=q1.y;
        }
        #pragma unroll
        for (int i = 0; i < 8; i++) {
            ull ad = pack_dup(a[i]);
            #pragma unroll
            for (int j = 0; j < 4; j++) ffma2(acc2[i][j], ad, bb[j]);
        }
        if (k < NK-1) {
            #pragma unroll
            for (int i = 0; i < 8; i++) a[i] = an[i];
            #pragma unroll
            for (int j = 0; j < 4; j++) bb[j] = bn[j];
        }
    }

    float cs[8];
    #pragma unroll
    for (int j = 0; j < 8; j++) cs[j] = 0.f;

    #pragma unroll
    for (int i = 0; i < 8; i++) {
        int row = row0 + ty*8 + i;
        float o[8];
        #pragma unroll
        for (int j = 0; j < 4; j++) {
            float2 c = unpack2(acc2[i][j]);
            o[j*2]   = fmaxf(c.x, 0.f);
            o[j*2+1] = fmaxf(c.y, 0.f);
        }
        #pragma unroll
        for (int j = 0; j < 8; j++) cs[j] += o[j];
        unsigned short hh[8], ll[8];
        #pragma unroll
        for (int j = 0; j < 8; j++) split_bf16(o[j], hh[j], ll[j]);
        uint2 hv0, lv0, hv1, lv1;
        hv0.x = (unsigned)hh[0] | ((unsigned)hh[1] << 16);
        hv0.y = (unsigned)hh[2] | ((unsigned)hh[3] << 16);
        hv1.x = (unsigned)hh[4] | ((unsigned)hh[5] << 16);
        hv1.y = (unsigned)hh[6] | ((unsigned)hh[7] << 16);
        lv0.x = (unsigned)ll[0] | ((unsigned)ll[1] << 16);
        lv0.y = (unsigned)ll[2] | ((unsigned)ll[3] << 16);
        lv1.x = (unsigned)ll[4] | ((unsigned)ll[5] << 16);
        lv1.y = (unsigned)ll[6] | ((unsigned)ll[7] << 16);
        *(uint2*)&g_rec1h[(size_t)row*NH + col0 + tx*4]      = hv0;
        *(uint2*)&g_rec1h[(size_t)row*NH + col0 + 64 + tx*4] = hv1;
        *(uint2*)&g_rec1l[(size_t)row*NH + col0 + tx*4]      = lv0;
        *(uint2*)&g_rec1l[(size_t)row*NH + col0 + 64 + tx*4] = lv1;
    }

    __syncthreads();
    float* scs = As;   // 128 cols x 16 ty
    #pragma unroll
    for (int j = 0; j < 8; j++) {
        int cl = ((j >= 4) ? 64 : 0) + tx*4 + (j & 3);
        scs[cl*16 + ty] = cs[j];
    }
    __syncthreads();
    if (tid < 128) {
        float ssum = 0.f;
        #pragma unroll
        for (int t = 0; t < 16; t++) ssum += scs[tid*16 + t];
        atomicAdd(&g_h1sum[b*NH + col0 + tid], ssum);
    }
}

// ---------------- kernel 3: rec2 via mma.sync bf16x3 (HMMA), fused ae_loss ----------------
// CTA 128 rows x 128 cols, grid (2, 512). 8 warps: wr = wid>>1 (row group of 32), wc = wid&1 (col group of 64).
// Warp tile 32x64: mb=0,1 (m16 blocks), ns=0..7 (n8 steps). K = 256 in 16 chunks of 16.
__global__ void __launch_bounds__(256) rec2_mma_kernel(const float* __restrict__ f) {
    __shared__ float red_sm[256];
    int tid = threadIdx.x;
    int wid = tid >> 5, lane = tid & 31;
    int g = lane >> 2, tg = lane & 3;
    int col0 = blockIdx.x * 128;
    int row0 = blockIdx.y * 128;
    int b = row0 >> 9;
    int s00 = row0 & 511;

    int wr = wid >> 1, wc = wid & 1;
    int rw = row0 + wr*32;            // warp row base
    int cw = col0 + wc*64;            // warp col base

    float acc[2][8][4];
    #pragma unroll
    for (int mb = 0; mb < 2; mb++)
        #pragma unroll
        for (int ns = 0; ns < 8; ns++)
            #pragma unroll
            for (int q = 0; q < 4; q++) acc[mb][ns][q] = 0.f;

    // row/col bases for this thread's fragments
    const size_t arow0 = (size_t)(rw + g) * NH;           // + mb*16*NH, + 8*NH
    const size_t brow0 = (size_t)(cw + g) * NH;           // + ns*8*NH

    for (int k0 = 0; k0 < NH; k0 += 16) {
        int ka = k0 + tg*2;
        // A fragments hi/lo: a[mb][4]
        uint32_t ah[2][4], al[2][4];
        #pragma unroll
        for (int mb = 0; mb < 2; mb++) {
            size_t base = arow0 + (size_t)mb*16*NH + ka;
            ah[mb][0] = *(const uint32_t*)&g_rec1h[base];
            ah[mb][1] = *(const uint32_t*)&g_rec1h[base + 8*NH];
            ah[mb][2] = *(const uint32_t*)&g_rec1h[base + 8];
            ah[mb][3] = *(const uint32_t*)&g_rec1h[base + 8*NH + 8];
            al[mb][0] = *(const uint32_t*)&g_rec1l[base];
            al[mb][1] = *(const uint32_t*)&g_rec1l[base + 8*NH];
            al[mb][2] = *(const uint32_t*)&g_rec1l[base + 8];
            al[mb][3] = *(const uint32_t*)&g_rec1l[base + 8*NH + 8];
        }
        // B fragments hi: bh[ns][2]
        uint32_t bh[8][2];
        #pragma unroll
        for (int ns = 0; ns < 8; ns++) {
            size_t base = brow0 + (size_t)ns*8*NH + ka;
            bh[ns][0] = *(const uint32_t*)&g_rv2hT[base];
            bh[ns][1] = *(const uint32_t*)&g_rv2hT[base + 8];
        }
        // combo 1: Ah * Bh ; combo 2: Al * Bh
        #pragma unroll
        for (int mb = 0; mb < 2; mb++)
            #pragma unroll
            for (int ns = 0; ns < 8; ns++) {
                mma16816(acc[mb][ns], ah[mb], bh[ns]);
                mma16816(acc[mb][ns], al[mb], bh[ns]);
            }
        // B fragments lo (reuse bh regs)
        #pragma unroll
        for (int ns = 0; ns < 8; ns++) {
            size_t base = brow0 + (size_t)ns*8*NH + ka;
            bh[ns][0] = *(const uint32_t*)&g_rv2lT[base];
            bh[ns][1] = *(const uint32_t*)&g_rv2lT[base + 8];
        }
        // combo 3: Ah * Bl
        #pragma unroll
        for (int mb = 0; mb < 2; mb++)
            #pragma unroll
            for (int ns = 0; ns < 8; ns++)
                mma16816(acc[mb][ns], ah[mb], bh[ns]);
    }

    // epilogue: ae only (pred comes from the exact h1sum@rv2 path)
    // frag (mb, ns): c0 -> (row rw+mb*16+g,   col cw+ns*8+tg*2)
    //               c1 -> (row rw+mb*16+g,   col+1)
    //               c2 -> (row rw+mb*16+g+8, col)
    //               c3 -> (row rw+mb*16+g+8, col+1)
    float ae = 0.f;
    #pragma unroll
    for (int mb = 0; mb < 2; mb++) {
        int r0g = rw + mb*16 + g;
        float in0 = g_invnorm[r0g];
        float in1 = g_invnorm[r0g + 8];
        int sA = s00 + (r0g - row0);
        int sB = sA + 8;
        #pragma unroll
        for (int ns = 0; ns < 8; ns++) {
            int col = cw + ns*8 + tg*2;
            const float* fp0 = f + ((size_t)(b*ND + col))*NS;
            const float* fp1 = fp0 + NS;
            float d0 = fp0[sA]*in0 - acc[mb][ns][0];
            float d1 = fp1[sA]*in0 - acc[mb][ns][1];
            float d2 = fp0[sB]*in1 - acc[mb][ns][2];
            float d3 = fp1[sB]*in1 - acc[mb][ns][3];
            ae += d0*d0 + d1*d1 + d2*d2 + d3*d3;
        }
    }
    red_sm[tid] = ae;
    __syncthreads();
    for (int st = 128; st > 0; st >>= 1) { if (tid < st) red_sm[tid] += red_sm[tid+st]; __syncthreads(); }
    if (tid == 0) atomicAdd(&g_ae, red_sm[0]);
}

// ---------------- g_mean = g_h1sum @ rv2 (exact fp32 path for pred) ----------------
__global__ void h1mat_kernel(const float* __restrict__ rv2) {
    __shared__ float hs[NH];
    int b = blockIdx.x, d = threadIdx.x;
    hs[d] = g_h1sum[b*NH + d];
    __syncthreads();
    float acc = 0.f;
    #pragma unroll 8
    for (int h = 0; h < NH; h++) acc += hs[h] * rv2[h*ND + d];
    g_mean[b*ND + d] = acc;
}

// ---------------- final ----------------
__global__ void final_kernel(const float* __restrict__ Wc, const float* __restrict__ bc,
                             float* __restrict__ out) {
    int tid = threadIdx.x;
    int b = tid >> 1, c = tid & 1;
    float acc = 0.f;
    for (int d = 0; d < ND; d++) acc += g_mean[b*ND + d] * Wc[d*2 + c];
    out[OUT_PRED + b*2 + c] = acc * (1.0f/512.0f) + bc[c];
    if (tid == 0) {
        out[OUT_SCAL0] = 0.0f;
        out[OUT_SIM]   = -g_sim / (float)(NK * (NB/4));
        out[OUT_FAR]   = g_far;
        out[OUT_AE]    = g_ae / (float)((size_t)NROWS * ND);
    }
}

extern "C" void kernel_launch(void* const* d_in, const int* in_sizes, int n_in,
                              void* d_out, int out_size) {
    const float* f   = (const float*)d_in[0];   // [B,D,S]
    const float* tv  = (const float*)d_in[2];   // [D,K]
    const float* rv1 = (const float*)d_in[3];   // [K,H]
    const float* rv2 = (const float*)d_in[4];   // [H,D]
    const float* Wc  = (const float*)d_in[5];   // [D,NCLS]
    const float* bc  = (const float*)d_in[6];   // [NCLS]
    float* out = (float*)d_out;

    cudaFuncSetAttribute(rec1_kernel, cudaFuncAttributeMaxDynamicSharedMemorySize, REC1_SMEM);
    cudaFuncSetAttribute(topsel_kernel, cudaFuncAttributeMaxDynamicSharedMemorySize, TSEL_SMEM);

    prep_kernel<<<1, 256>>>(tv);
    convrv2_kernel<<<NH, 256>>>(rv2);
    topic_kernel<<<NROWS/256, 256>>>(f, out + OUT_NN);
    topsel_kernel<<<NK, 1024, TSEL_SMEM>>>();
    rec1_kernel<<<dim3(2, 512), 256, REC1_SMEM>>>(rv1);
    rec2_mma_kernel<<<dim3(2, 512), 256>>>(f);
    h1mat_kernel<<<NB, 256>>>(rv2);
    final_kernel<<<1, 256>>>(Wc, bc, out);
}